// round 13
// baseline (speedup 1.0000x reference)
#include <cuda_runtime.h>
#include <cuda_fp16.h>
#include <cstddef>

#define NN 8192
#define FF 256
#define CAP 192       // per-row neighbor cap; mean 83, 6-sigma = 138
#define PSCALE 8192.0f

__device__ __half g_P[(size_t)NN * FF];   // P = PSCALE * exp(f-M) * h_prime  (fp16)
__device__ float  g_fdst[NN];
__device__ float  g_gv[NN];               // exp(f-M), fp32
__device__ float  g_wv[FF];               // w @ (w_a @ a[2:4])
__device__ unsigned g_maxbits;
__device__ unsigned short g_nbr[NN][CAP]; // compacted neighbor lists (u16)
__device__ float  g_den[NN];
__device__ int    g_nnz[NN];

__device__ __forceinline__ unsigned fkey(float f) {
    unsigned b = __float_as_uint(f);
    return b ^ ((b & 0x80000000u) ? 0xFFFFFFFFu : 0x80000000u);
}
__device__ __forceinline__ float funkey(unsigned k) {
    unsigned b = (k & 0x80000000u) ? (k ^ 0x80000000u) : (k ^ 0xFFFFFFFFu);
    return __uint_as_float(b);
}

// ---------------------------------------------------------------------------
// Kernel 0: wv[k] = sum_o w[k,o] * va[o],  va = w_a @ a[2:4]. Resets maxbits.
// ---------------------------------------------------------------------------
__global__ __launch_bounds__(1024) void prep_kernel(const float* __restrict__ w,
                                                    const float* __restrict__ w_a,
                                                    const float* __restrict__ a) {
    __shared__ float va[256];
    const int tid = threadIdx.x;
    if (tid < 256) va[tid] = w_a[2 * tid] * a[2] + w_a[2 * tid + 1] * a[3];
    if (tid == 0) g_maxbits = 0u;
    __syncthreads();

    const int lane = tid & 31;
    const int warp = tid >> 5;
#pragma unroll
    for (int rr = 0; rr < 8; rr++) {
        const int r = warp + rr * 32;
        float s = 0.f;
#pragma unroll
        for (int t = 0; t < 8; t++) {
            const int o = t * 32 + lane;
            s += w[(size_t)r * 256 + o] * va[o];
        }
#pragma unroll
        for (int off = 16; off > 0; off >>= 1) s += __shfl_xor_sync(0xffffffffu, s, off);
        if (lane == 0) g_wv[r] = s;
    }
}

// ---------------------------------------------------------------------------
// Kernel 1: f_dst[i] = node[i,:] . wv ; global max via atomicMax on monotone
// key (order-independent => deterministic). f_src cancels in the row softmax.
// ---------------------------------------------------------------------------
__global__ __launch_bounds__(256) void fdst_kernel(const float* __restrict__ node) {
    __shared__ float wv[256];
    __shared__ float s_f[8];
    const int tid = threadIdx.x;
    wv[tid] = g_wv[tid];
    __syncthreads();

    const int lane = tid & 31;
    const int warp = tid >> 5;
    const int row = blockIdx.x * 8 + warp;
    const float* np = &node[(size_t)row * 256];

    float s = 0.f;
#pragma unroll
    for (int k = 0; k < 8; k++) {
        int c = lane + k * 32;
        s += np[c] * wv[c];
    }
#pragma unroll
    for (int o = 16; o > 0; o >>= 1) s += __shfl_xor_sync(0xffffffffu, s, o);
    if (lane == 0) { g_fdst[row] = s; s_f[warp] = s; }
    __syncthreads();
    if (tid == 0) {
        float m = s_f[0];
#pragma unroll
        for (int w = 1; w < 8; w++) m = fmaxf(m, s_f[w]);
        atomicMax(&g_maxbits, fkey(m));
    }
}

// ---------------------------------------------------------------------------
// Kernel 2: g_gv[i] = exp(f_dst[i] - M)
// ---------------------------------------------------------------------------
__global__ __launch_bounds__(1024) void gv_kernel() {
    const int row = blockIdx.x * 1024 + threadIdx.x;
    const float M = funkey(g_maxbits);
    g_gv[row] = __expf(g_fdst[row] - M);
}

// ---------------------------------------------------------------------------
// Kernel 3 (FUSED): block-specialized, no inter-block dependency.
//  bid < 256  : GEMM  P[i,:] = half(PSCALE*gv[i]*(node[i,:]@w))
//               (128x64 tile, 8x4 microtile; h_prime never hits memory)
//  bid >= 256 : SCAN  4 rows each: coalesced presence-mask scan of Ahat,
//               compacted u16 neighbor list + denominator to global scratch.
// DRAM-bound scan overlaps compute-bound gemm on the same chip.
// ---------------------------------------------------------------------------
struct GemmS { float As[16][128]; float Bs[16][64]; };
struct ScanS { int flat[CAP + 64]; int cnt[8]; float den[8]; int off[9]; };
union FusedS { GemmS g; ScanS s; };

__global__ __launch_bounds__(256) void fused_kernel(const float* __restrict__ A,
                                                    const float* __restrict__ W,
                                                    const float* __restrict__ Ahat) {
    __shared__ FusedS sm;
    const int tid = threadIdx.x;
    const int bid = blockIdx.x;

    if (bid < 256) {
        // ---------------- GEMM role ----------------
        const int m0 = (bid >> 2) * 128;
        const int n0 = (bid & 3) * 64;

        const int tr = tid >> 4;
        const int tc = tid & 15;
        const int ar = tid >> 1;
        const int ac = (tid & 1) * 8;
        const int br = tid >> 4;
        const int bc = (tid & 15) * 4;

        float acc[8][4];
#pragma unroll
        for (int i = 0; i < 8; i++)
#pragma unroll
            for (int j = 0; j < 4; j++) acc[i][j] = 0.f;

        for (int k0 = 0; k0 < 256; k0 += 16) {
            float4 a0 = *(const float4*)&A[(size_t)(m0 + ar) * 256 + k0 + ac];
            float4 a1 = *(const float4*)&A[(size_t)(m0 + ar) * 256 + k0 + ac + 4];
            float4 b0 = *(const float4*)&W[(size_t)(k0 + br) * 256 + n0 + bc];

            __syncthreads();
            sm.g.As[ac + 0][ar] = a0.x; sm.g.As[ac + 1][ar] = a0.y;
            sm.g.As[ac + 2][ar] = a0.z; sm.g.As[ac + 3][ar] = a0.w;
            sm.g.As[ac + 4][ar] = a1.x; sm.g.As[ac + 5][ar] = a1.y;
            sm.g.As[ac + 6][ar] = a1.z; sm.g.As[ac + 7][ar] = a1.w;
            *(float4*)&sm.g.Bs[br][bc] = b0;
            __syncthreads();

#pragma unroll
            for (int k = 0; k < 16; k++) {
                float4 x0 = *(const float4*)&sm.g.As[k][tr * 8];
                float4 x1 = *(const float4*)&sm.g.As[k][tr * 8 + 4];
                float4 y0 = *(const float4*)&sm.g.Bs[k][tc * 4];
                float ra[8] = {x0.x, x0.y, x0.z, x0.w, x1.x, x1.y, x1.z, x1.w};
                float rb[4] = {y0.x, y0.y, y0.z, y0.w};
#pragma unroll
                for (int i = 0; i < 8; i++)
#pragma unroll
                    for (int j = 0; j < 4; j++) acc[i][j] += ra[i] * rb[j];
            }
        }

#pragma unroll
        for (int i = 0; i < 8; i++) {
            const int row = m0 + tr * 8 + i;
            const float gs = g_gv[row] * PSCALE;
            __half2 h01 = __floats2half2_rn(acc[i][0] * gs, acc[i][1] * gs);
            __half2 h23 = __floats2half2_rn(acc[i][2] * gs, acc[i][3] * gs);
            __half2* dst = (__half2*)&g_P[(size_t)row * 256 + n0 + tc * 4];
            dst[0] = h01;
            dst[1] = h23;
        }
    } else {
        // ---------------- SCAN role: 4 rows ----------------
        const int lane = tid & 31;
        const int wid = tid >> 5;
        const int r0 = (bid - 256) * 4;

        for (int rr = 0; rr < 4; rr++) {
            const size_t row = r0 + rr;
            const float4* arow = (const float4*)(Ahat + row * NN);
            unsigned mask = 0u;
#pragma unroll
            for (int k = 0; k < 8; k++) {
                float4 v = __ldcs(&arow[wid * 256 + k * 32 + lane]);
                if (v.x > 0.f) mask |= 1u << (4 * k + 0);
                if (v.y > 0.f) mask |= 1u << (4 * k + 1);
                if (v.z > 0.f) mask |= 1u << (4 * k + 2);
                if (v.w > 0.f) mask |= 1u << (4 * k + 3);
            }
            int cnt = __popc(mask);

            int pre = cnt;
#pragma unroll
            for (int o = 1; o < 32; o <<= 1) {
                int n = __shfl_up_sync(0xffffffffu, pre, o);
                if (lane >= o) pre += n;
            }
            if (lane == 31) sm.s.cnt[wid] = pre;
            __syncthreads();
            if (tid == 0) {
                int o = 0;
#pragma unroll
                for (int w = 0; w < 8; w++) { sm.s.off[w] = o; o += sm.s.cnt[w]; }
                sm.s.off[8] = o;
            }
            __syncthreads();

            int off = sm.s.off[wid] + (pre - cnt);
            float denl = 0.f;
            const int cbase = wid * 1024 + lane * 4;
            unsigned m = mask;
            while (m) {
                int b = __ffs(m) - 1;
                int col = cbase + (b >> 2) * 128 + (b & 3);
                if (off < CAP) sm.s.flat[off] = col;
                off++;
                denl += g_gv[col];
                m &= m - 1u;
            }

#pragma unroll
            for (int o = 16; o > 0; o >>= 1) denl += __shfl_xor_sync(0xffffffffu, denl, o);
            if (lane == 0) sm.s.den[wid] = denl;
            __syncthreads();

            int nnz = sm.s.off[8]; if (nnz > CAP) nnz = CAP;
            if (tid < nnz) g_nbr[row][tid] = (unsigned short)sm.s.flat[tid];
            if (tid == 0) {
                g_nnz[row] = nnz;
                g_den[row] = ((sm.s.den[0] + sm.s.den[1]) + (sm.s.den[2] + sm.s.den[3])) +
                             ((sm.s.den[4] + sm.s.den[5]) + (sm.s.den[6] + sm.s.den[7]));
            }
            __syncthreads();
        }
    }
}

// ---------------------------------------------------------------------------
// Kernel 4: gather. out[i] = relu( sum P[j] / (PSCALE * den[i]) )
// One CTA per row; 4 groups x 64 threads; group g handles j==g (mod 4);
// half4 (uint2) loads, fp32 accumulation, fixed-order smem reduction.
// ---------------------------------------------------------------------------
__global__ __launch_bounds__(256) void gather_kernel(float* __restrict__ out) {
    __shared__ int   s_idx[CAP];
    __shared__ float s_part[4 * 256];

    const int tid = threadIdx.x;
    const size_t row = blockIdx.x;

    const int nnz = g_nnz[row];
    const float den = g_den[row];
    if (tid < nnz) s_idx[tid] = g_nbr[row][tid];
    __syncthreads();

    const int g = tid >> 6;    // group 0..3
    const int c = tid & 63;    // half4 (uint2) index within row

    float ax = 0.f, ay = 0.f, az = 0.f, aw = 0.f;
    float bx = 0.f, by = 0.f, bz = 0.f, bw = 0.f;

    int j = g;
    for (; j + 4 < nnz; j += 8) {
        uint2 v0 = __ldg((const uint2*)&g_P[(size_t)s_idx[j + 0] * 256] + c);
        uint2 v1 = __ldg((const uint2*)&g_P[(size_t)s_idx[j + 4] * 256] + c);
        float2 l0 = __half22float2(*(const __half2*)&v0.x);
        float2 h0 = __half22float2(*(const __half2*)&v0.y);
        float2 l1 = __half22float2(*(const __half2*)&v1.x);
        float2 h1 = __half22float2(*(const __half2*)&v1.y);
        ax += l0.x; ay += l0.y; az += h0.x; aw += h0.y;
        bx += l1.x; by += l1.y; bz += h1.x; bw += h1.y;
    }
    for (; j < nnz; j += 4) {
        uint2 v0 = __ldg((const uint2*)&g_P[(size_t)s_idx[j] * 256] + c);
        float2 l0 = __half22float2(*(const __half2*)&v0.x);
        float2 h0 = __half22float2(*(const __half2*)&v0.y);
        ax += l0.x; ay += l0.y; az += h0.x; aw += h0.y;
    }
    ax += bx; ay += by; az += bz; aw += bw;

    *(float4*)&s_part[g * 256 + c * 4] = make_float4(ax, ay, az, aw);
    __syncthreads();

    const float invd = 1.f / (den * PSCALE);
    float r = ((s_part[0 * 256 + tid] + s_part[1 * 256 + tid]) +
               (s_part[2 * 256 + tid] + s_part[3 * 256 + tid]));
    out[row * 256 + tid] = fmaxf(r * invd, 0.f);
}

// ---------------------------------------------------------------------------
extern "C" void kernel_launch(void* const* d_in, const int* in_sizes, int n_in,
                              void* d_out, int out_size) {
    (void)in_sizes; (void)n_in; (void)out_size;
    const float* node = (const float*)d_in[0];
    const float* Ahat = (const float*)d_in[1];
    const float* w    = (const float*)d_in[2];
    const float* w_a  = (const float*)d_in[3];
    const float* a    = (const float*)d_in[4];
    float* out = (float*)d_out;

    prep_kernel<<<1, 1024>>>(w, w_a, a);
    fdst_kernel<<<NN / 8, 256>>>(node);
    gv_kernel<<<NN / 1024, 1024>>>();
    fused_kernel<<<256 + NN / 4, 256>>>(node, w, Ahat);
    gather_kernel<<<NN, 256>>>(out);
}

// round 15
// speedup vs baseline: 1.1250x; 1.1250x over previous
#include <cuda_runtime.h>
#include <cuda_fp16.h>
#include <cstddef>

#define NN 8192
#define FF 256
#define CAP 192       // per-row neighbor cap; mean 83, 6-sigma = 138
#define PSCALE 8192.0f

__device__ __half g_P[(size_t)NN * FF];   // P = PSCALE * exp(f-M) * h_prime  (fp16)
__device__ float  g_fdst[NN];
__device__ float  g_gv[NN];               // exp(f-M), fp32
__device__ float  g_wv[FF];               // w @ (w_a @ a[2:4])
__device__ unsigned g_maxbits;
__device__ unsigned short g_nbr[NN][CAP]; // compacted neighbor lists (u16)
__device__ float  g_den[NN];
__device__ int    g_nnz[NN];

__device__ __forceinline__ unsigned fkey(float f) {
    unsigned b = __float_as_uint(f);
    return b ^ ((b & 0x80000000u) ? 0xFFFFFFFFu : 0x80000000u);
}
__device__ __forceinline__ float funkey(unsigned k) {
    unsigned b = (k & 0x80000000u) ? (k ^ 0x80000000u) : (k ^ 0xFFFFFFFFu);
    return __uint_as_float(b);
}

// ---------------------------------------------------------------------------
// Kernel 0: wv[k] = sum_o w[k,o] * va[o],  va = w_a @ a[2:4]. Resets maxbits.
// ---------------------------------------------------------------------------
__global__ __launch_bounds__(1024) void prep_kernel(const float* __restrict__ w,
                                                    const float* __restrict__ w_a,
                                                    const float* __restrict__ a) {
    __shared__ float va[256];
    const int tid = threadIdx.x;
    if (tid < 256) va[tid] = w_a[2 * tid] * a[2] + w_a[2 * tid + 1] * a[3];
    if (tid == 0) g_maxbits = 0u;
    __syncthreads();

    const int lane = tid & 31;
    const int warp = tid >> 5;
#pragma unroll
    for (int rr = 0; rr < 8; rr++) {
        const int r = warp + rr * 32;
        float s = 0.f;
#pragma unroll
        for (int t = 0; t < 8; t++) {
            const int o = t * 32 + lane;
            s += w[(size_t)r * 256 + o] * va[o];
        }
#pragma unroll
        for (int off = 16; off > 0; off >>= 1) s += __shfl_xor_sync(0xffffffffu, s, off);
        if (lane == 0) g_wv[r] = s;
    }
}

// ---------------------------------------------------------------------------
// Kernel 1: f_dst[i] = node[i,:] . wv ; global max via atomicMax on monotone
// key (order-independent => deterministic). f_src cancels in the row softmax.
// ---------------------------------------------------------------------------
__global__ __launch_bounds__(256) void fdst_kernel(const float* __restrict__ node) {
    __shared__ float wv[256];
    __shared__ float s_f[8];
    const int tid = threadIdx.x;
    wv[tid] = g_wv[tid];
    __syncthreads();

    const int lane = tid & 31;
    const int warp = tid >> 5;
    const int row = blockIdx.x * 8 + warp;
    const float* np = &node[(size_t)row * 256];

    float s = 0.f;
#pragma unroll
    for (int k = 0; k < 8; k++) {
        int c = lane + k * 32;
        s += np[c] * wv[c];
    }
#pragma unroll
    for (int o = 16; o > 0; o >>= 1) s += __shfl_xor_sync(0xffffffffu, s, o);
    if (lane == 0) { g_fdst[row] = s; s_f[warp] = s; }
    __syncthreads();
    if (tid == 0) {
        float m = s_f[0];
#pragma unroll
        for (int w = 1; w < 8; w++) m = fmaxf(m, s_f[w]);
        atomicMax(&g_maxbits, fkey(m));
    }
}

// ---------------------------------------------------------------------------
// Kernel 2: g_gv[i] = exp(f_dst[i] - M)
// ---------------------------------------------------------------------------
__global__ __launch_bounds__(1024) void gv_kernel() {
    const int row = blockIdx.x * 1024 + threadIdx.x;
    const float M = funkey(g_maxbits);
    g_gv[row] = __expf(g_fdst[row] - M);
}

// ---------------------------------------------------------------------------
// Kernel 3: GEMM + P epilogue:  P[i,:] = half(PSCALE*gv[i]*(node[i,:]@w))
// 128x64 tile, 256 threads, 8x4 microtile. grid = 256 CTAs.
// Runs on a PARALLEL GRAPH BRANCH concurrent with scan_kernel.
// ---------------------------------------------------------------------------
__global__ __launch_bounds__(256) void gemm_kernel(const float* __restrict__ A,
                                                   const float* __restrict__ W) {
    __shared__ float As[16][128];
    __shared__ float Bs[16][64];

    const int m0 = blockIdx.y * 128;
    const int n0 = blockIdx.x * 64;
    const int tid = threadIdx.x;

    const int tr = tid >> 4;
    const int tc = tid & 15;
    const int ar = tid >> 1;
    const int ac = (tid & 1) * 8;
    const int br = tid >> 4;
    const int bc = (tid & 15) * 4;

    float acc[8][4];
#pragma unroll
    for (int i = 0; i < 8; i++)
#pragma unroll
        for (int j = 0; j < 4; j++) acc[i][j] = 0.f;

    for (int k0 = 0; k0 < 256; k0 += 16) {
        float4 a0 = *(const float4*)&A[(size_t)(m0 + ar) * 256 + k0 + ac];
        float4 a1 = *(const float4*)&A[(size_t)(m0 + ar) * 256 + k0 + ac + 4];
        float4 b0 = *(const float4*)&W[(size_t)(k0 + br) * 256 + n0 + bc];

        __syncthreads();
        As[ac + 0][ar] = a0.x; As[ac + 1][ar] = a0.y;
        As[ac + 2][ar] = a0.z; As[ac + 3][ar] = a0.w;
        As[ac + 4][ar] = a1.x; As[ac + 5][ar] = a1.y;
        As[ac + 6][ar] = a1.z; As[ac + 7][ar] = a1.w;
        *(float4*)&Bs[br][bc] = b0;
        __syncthreads();

#pragma unroll
        for (int k = 0; k < 16; k++) {
            float4 x0 = *(const float4*)&As[k][tr * 8];
            float4 x1 = *(const float4*)&As[k][tr * 8 + 4];
            float4 y0 = *(const float4*)&Bs[k][tc * 4];
            float ra[8] = {x0.x, x0.y, x0.z, x0.w, x1.x, x1.y, x1.z, x1.w};
            float rb[4] = {y0.x, y0.y, y0.z, y0.w};
#pragma unroll
            for (int i = 0; i < 8; i++)
#pragma unroll
                for (int j = 0; j < 4; j++) acc[i][j] += ra[i] * rb[j];
        }
    }

#pragma unroll
    for (int i = 0; i < 8; i++) {
        const int row = m0 + tr * 8 + i;
        const float gs = g_gv[row] * PSCALE;
        __half2 h01 = __floats2half2_rn(acc[i][0] * gs, acc[i][1] * gs);
        __half2 h23 = __floats2half2_rn(acc[i][2] * gs, acc[i][3] * gs);
        __half2* dst = (__half2*)&g_P[(size_t)row * 256 + n0 + tc * 4];
        dst[0] = h01;
        dst[1] = h23;
    }
}

// ---------------------------------------------------------------------------
// Kernel 4: SCAN. One CTA per row; coalesced presence-mask scan of Ahat;
// writes compacted u16 neighbor list + denominator. No dependency on P,
// so it runs concurrently with gemm_kernel. Low regs -> high occ -> DRAM MLP.
// ---------------------------------------------------------------------------
__global__ __launch_bounds__(256) void scan_kernel(const float* __restrict__ Ahat) {
    __shared__ int   s_flat[CAP + 64];
    __shared__ int   s_cnt[8];
    __shared__ float s_den[8];
    __shared__ int   s_off[9];

    const int tid = threadIdx.x;
    const int lane = tid & 31;
    const int wid = tid >> 5;
    const size_t row = blockIdx.x;

    const float4* arow = (const float4*)(Ahat + row * NN);
    unsigned mask = 0u;
#pragma unroll
    for (int k = 0; k < 8; k++) {
        float4 v = __ldcs(&arow[wid * 256 + k * 32 + lane]);
        if (v.x > 0.f) mask |= 1u << (4 * k + 0);
        if (v.y > 0.f) mask |= 1u << (4 * k + 1);
        if (v.z > 0.f) mask |= 1u << (4 * k + 2);
        if (v.w > 0.f) mask |= 1u << (4 * k + 3);
    }
    int cnt = __popc(mask);

    int pre = cnt;
#pragma unroll
    for (int o = 1; o < 32; o <<= 1) {
        int n = __shfl_up_sync(0xffffffffu, pre, o);
        if (lane >= o) pre += n;
    }
    if (lane == 31) s_cnt[wid] = pre;
    __syncthreads();
    if (tid == 0) {
        int o = 0;
#pragma unroll
        for (int w = 0; w < 8; w++) { s_off[w] = o; o += s_cnt[w]; }
        s_off[8] = o;
    }
    __syncthreads();

    int off = s_off[wid] + (pre - cnt);
    float denl = 0.f;
    const int cbase = wid * 1024 + lane * 4;
    unsigned m = mask;
    while (m) {
        int b = __ffs(m) - 1;
        int col = cbase + (b >> 2) * 128 + (b & 3);
        if (off < CAP) s_flat[off] = col;
        off++;
        denl += g_gv[col];
        m &= m - 1u;
    }

#pragma unroll
    for (int o = 16; o > 0; o >>= 1) denl += __shfl_xor_sync(0xffffffffu, denl, o);
    if (lane == 0) s_den[wid] = denl;
    __syncthreads();

    int nnz = s_off[8]; if (nnz > CAP) nnz = CAP;
    if (tid < nnz) g_nbr[row][tid] = (unsigned short)s_flat[tid];
    if (tid == 0) {
        g_nnz[row] = nnz;
        g_den[row] = ((s_den[0] + s_den[1]) + (s_den[2] + s_den[3])) +
                     ((s_den[4] + s_den[5]) + (s_den[6] + s_den[7]));
    }
}

// ---------------------------------------------------------------------------
// Kernel 5: gather. out[i] = relu( sum P[j] / (PSCALE * den[i]) )
// One CTA per row; 4 groups x 64 threads; group g handles j==g (mod 4);
// half4 (uint2) loads, fp32 accumulation, fixed-order smem reduction.
// ---------------------------------------------------------------------------
__global__ __launch_bounds__(256) void gather_kernel(float* __restrict__ out) {
    __shared__ int   s_idx[CAP];
    __shared__ float s_part[4 * 256];

    const int tid = threadIdx.x;
    const size_t row = blockIdx.x;

    const int nnz = g_nnz[row];
    const float den = g_den[row];
    if (tid < nnz) s_idx[tid] = g_nbr[row][tid];
    __syncthreads();

    const int g = tid >> 6;    // group 0..3
    const int c = tid & 63;    // half4 (uint2) index within row

    float ax = 0.f, ay = 0.f, az = 0.f, aw = 0.f;
    float bx = 0.f, by = 0.f, bz = 0.f, bw = 0.f;

    int j = g;
    for (; j + 4 < nnz; j += 8) {
        uint2 v0 = __ldg((const uint2*)&g_P[(size_t)s_idx[j + 0] * 256] + c);
        uint2 v1 = __ldg((const uint2*)&g_P[(size_t)s_idx[j + 4] * 256] + c);
        float2 l0 = __half22float2(*(const __half2*)&v0.x);
        float2 h0 = __half22float2(*(const __half2*)&v0.y);
        float2 l1 = __half22float2(*(const __half2*)&v1.x);
        float2 h1 = __half22float2(*(const __half2*)&v1.y);
        ax += l0.x; ay += l0.y; az += h0.x; aw += h0.y;
        bx += l1.x; by += l1.y; bz += h1.x; bw += h1.y;
    }
    for (; j < nnz; j += 4) {
        uint2 v0 = __ldg((const uint2*)&g_P[(size_t)s_idx[j] * 256] + c);
        float2 l0 = __half22float2(*(const __half2*)&v0.x);
        float2 h0 = __half22float2(*(const __half2*)&v0.y);
        ax += l0.x; ay += l0.y; az += h0.x; aw += h0.y;
    }
    ax += bx; ay += by; az += bz; aw += bw;

    *(float4*)&s_part[g * 256 + c * 4] = make_float4(ax, ay, az, aw);
    __syncthreads();

    const float invd = 1.f / (den * PSCALE);
    float r = ((s_part[0 * 256 + tid] + s_part[1 * 256 + tid]) +
               (s_part[2 * 256 + tid] + s_part[3 * 256 + tid]));
    out[row * 256 + tid] = fmaxf(r * invd, 0.f);
}

// ---------------------------------------------------------------------------
// Launch: prep -> fdst -> gv -> [ gemm (stream2) || scan (main) ] -> gather
// Fork/join via events becomes parallel branches in the captured graph.
// Stream/events are lazily-created host objects; captured work is identical
// on every call (graph content deterministic).
// ---------------------------------------------------------------------------
extern "C" void kernel_launch(void* const* d_in, const int* in_sizes, int n_in,
                              void* d_out, int out_size) {
    (void)in_sizes; (void)n_in; (void)out_size;
    const float* node = (const float*)d_in[0];
    const float* Ahat = (const float*)d_in[1];
    const float* w    = (const float*)d_in[2];
    const float* w_a  = (const float*)d_in[3];
    const float* a    = (const float*)d_in[4];
    float* out = (float*)d_out;

    static cudaStream_t s2 = nullptr;
    static cudaEvent_t e_fork = nullptr, e_join = nullptr;
    if (s2 == nullptr) {
        cudaStreamCreateWithFlags(&s2, cudaStreamNonBlocking);
        cudaEventCreateWithFlags(&e_fork, cudaEventDisableTiming);
        cudaEventCreateWithFlags(&e_join, cudaEventDisableTiming);
    }

    prep_kernel<<<1, 1024>>>(w, w_a, a);
    fdst_kernel<<<NN / 8, 256>>>(node);
    gv_kernel<<<NN / 1024, 1024>>>();

    // fork: gemm on s2, concurrent with scan on the main stream
    cudaEventRecord(e_fork, 0);
    cudaStreamWaitEvent(s2, e_fork, 0);
    dim3 ggrid(4, 64);
    gemm_kernel<<<ggrid, 256, 0, s2>>>(node, w);
    cudaEventRecord(e_join, s2);

    scan_kernel<<<NN, 256>>>(Ahat);

    // join: gather needs both P (gemm) and the lists (scan)
    cudaStreamWaitEvent(0, e_join, 0);
    gather_kernel<<<NN, 256>>>(out);
}

// round 17
// speedup vs baseline: 1.1550x; 1.0267x over previous
#include <cuda_runtime.h>
#include <cuda_fp16.h>
#include <cstddef>

#define NN 8192
#define FF 256
#define CAP 192       // per-row neighbor cap; mean 83, 6-sigma = 138
#define PSCALE 8192.0f

__device__ __half g_P[(size_t)NN * FF];   // P = PSCALE * exp(f-M) * h_prime  (fp16)
__device__ float  g_fdst[NN];
__device__ float  g_gv[NN];               // exp(f-M), fp32
__device__ float  g_wv[FF];               // w @ (w_a @ a[2:4])
__device__ unsigned g_maxbits;
__device__ unsigned short g_nbr[NN][CAP]; // compacted neighbor lists (u16)
__device__ float  g_den[NN];
__device__ int    g_nnz[NN];

__device__ __forceinline__ unsigned fkey(float f) {
    unsigned b = __float_as_uint(f);
    return b ^ ((b & 0x80000000u) ? 0xFFFFFFFFu : 0x80000000u);
}
__device__ __forceinline__ float funkey(unsigned k) {
    unsigned b = (k & 0x80000000u) ? (k ^ 0x80000000u) : (k ^ 0xFFFFFFFFu);
    return __uint_as_float(b);
}

// packed f32x2 helpers (Blackwell: fma.rn.f32x2 only reachable via PTX)
__device__ __forceinline__ unsigned long long splat2(float x) {
    unsigned long long r;
    unsigned u = __float_as_uint(x);
    asm("mov.b64 %0, {%1, %1};" : "=l"(r) : "r"(u));
    return r;
}
#define FMA2(acc, a, b) \
    asm("fma.rn.f32x2 %0, %1, %2, %0;" : "+l"(acc) : "l"(a), "l"(b))

// ---------------------------------------------------------------------------
// Kernel 0: wv[k] = sum_o w[k,o] * va[o],  va = w_a @ a[2:4]. Resets maxbits.
// ---------------------------------------------------------------------------
__global__ __launch_bounds__(1024) void prep_kernel(const float* __restrict__ w,
                                                    const float* __restrict__ w_a,
                                                    const float* __restrict__ a) {
    __shared__ float va[256];
    const int tid = threadIdx.x;
    if (tid < 256) va[tid] = w_a[2 * tid] * a[2] + w_a[2 * tid + 1] * a[3];
    if (tid == 0) g_maxbits = 0u;
    __syncthreads();

    const int lane = tid & 31;
    const int warp = tid >> 5;
#pragma unroll
    for (int rr = 0; rr < 8; rr++) {
        const int r = warp + rr * 32;
        float s = 0.f;
#pragma unroll
        for (int t = 0; t < 8; t++) {
            const int o = t * 32 + lane;
            s += w[(size_t)r * 256 + o] * va[o];
        }
#pragma unroll
        for (int off = 16; off > 0; off >>= 1) s += __shfl_xor_sync(0xffffffffu, s, off);
        if (lane == 0) g_wv[r] = s;
    }
}

// ---------------------------------------------------------------------------
// Kernel 1: f_dst[i] = node[i,:] . wv ; global max via atomicMax on monotone
// key (order-independent => deterministic). f_src cancels in the row softmax.
// ---------------------------------------------------------------------------
__global__ __launch_bounds__(256) void fdst_kernel(const float* __restrict__ node) {
    __shared__ float wv[256];
    __shared__ float s_f[8];
    const int tid = threadIdx.x;
    wv[tid] = g_wv[tid];
    __syncthreads();

    const int lane = tid & 31;
    const int warp = tid >> 5;
    const int row = blockIdx.x * 8 + warp;
    const float* np = &node[(size_t)row * 256];

    float s = 0.f;
#pragma unroll
    for (int k = 0; k < 8; k++) {
        int c = lane + k * 32;
        s += np[c] * wv[c];
    }
#pragma unroll
    for (int o = 16; o > 0; o >>= 1) s += __shfl_xor_sync(0xffffffffu, s, o);
    if (lane == 0) { g_fdst[row] = s; s_f[warp] = s; }
    __syncthreads();
    if (tid == 0) {
        float m = s_f[0];
#pragma unroll
        for (int w = 1; w < 8; w++) m = fmaxf(m, s_f[w]);
        atomicMax(&g_maxbits, fkey(m));
    }
}

// ---------------------------------------------------------------------------
// Kernel 2: g_gv[i] = exp(f_dst[i] - M)
// ---------------------------------------------------------------------------
__global__ __launch_bounds__(1024) void gv_kernel() {
    const int row = blockIdx.x * 1024 + threadIdx.x;
    const float M = funkey(g_maxbits);
    g_gv[row] = __expf(g_fdst[row] - M);
}

// ---------------------------------------------------------------------------
// Kernel 3: GEMM + P epilogue:  P[i,:] = half(PSCALE*gv[i]*(node[i,:]@w))
// 128x128 tile, 256 threads, 8x8 microtile with PACKED fma.rn.f32x2:
//  - acc[i][jp] holds output cols (2jp, 2jp+1) packed in 64 bits
//  - B-side packs come free from reinterpreting the float4 LDS registers
//  - A-side splat is one mov.b64 per i per k (alu pipe, overlaps fma pipe)
// Doubles FLOP/issue and drops LDS to 1.0 B/FLOP (was the binding pipe).
// ---------------------------------------------------------------------------
__global__ __launch_bounds__(256) void gemm_kernel(const float* __restrict__ A,
                                                   const float* __restrict__ W) {
    __shared__ float As[16][128];
    __shared__ float Bs[16][128];

    const int m0 = blockIdx.y * 128;
    const int n0 = blockIdx.x * 128;
    const int tid = threadIdx.x;

    const int tr = tid >> 4;        // 0..15 (M group of 8)
    const int tc = tid & 15;        // 0..15 (N group of 8)
    const int ar = tid >> 1;        // 0..127
    const int ac = (tid & 1) * 8;   // 0 or 8
    const int br = tid >> 4;        // 0..15
    const int bc = (tid & 15) * 8;  // 0..120

    unsigned long long acc[8][4];
#pragma unroll
    for (int i = 0; i < 8; i++)
#pragma unroll
        for (int j = 0; j < 4; j++) acc[i][j] = 0ull;

    for (int k0 = 0; k0 < 256; k0 += 16) {
        float4 a0 = *(const float4*)&A[(size_t)(m0 + ar) * 256 + k0 + ac];
        float4 a1 = *(const float4*)&A[(size_t)(m0 + ar) * 256 + k0 + ac + 4];
        float4 b0 = *(const float4*)&W[(size_t)(k0 + br) * 256 + n0 + bc];
        float4 b1 = *(const float4*)&W[(size_t)(k0 + br) * 256 + n0 + bc + 4];

        __syncthreads();
        As[ac + 0][ar] = a0.x; As[ac + 1][ar] = a0.y;
        As[ac + 2][ar] = a0.z; As[ac + 3][ar] = a0.w;
        As[ac + 4][ar] = a1.x; As[ac + 5][ar] = a1.y;
        As[ac + 6][ar] = a1.z; As[ac + 7][ar] = a1.w;
        *(float4*)&Bs[br][bc]     = b0;
        *(float4*)&Bs[br][bc + 4] = b1;
        __syncthreads();

#pragma unroll
        for (int k = 0; k < 16; k++) {
            float4 x0 = *(const float4*)&As[k][tr * 8];
            float4 x1 = *(const float4*)&As[k][tr * 8 + 4];
            float4 y0 = *(const float4*)&Bs[k][tc * 8];
            float4 y1 = *(const float4*)&Bs[k][tc * 8 + 4];

            // B pairs: free reinterpret of the LDS result registers
            unsigned long long rb0 = *(unsigned long long*)&y0.x;   // {y0.x,y0.y}
            unsigned long long rb1 = *(unsigned long long*)&y0.z;   // {y0.z,y0.w}
            unsigned long long rb2 = *(unsigned long long*)&y1.x;
            unsigned long long rb3 = *(unsigned long long*)&y1.z;

            float ra[8] = {x0.x, x0.y, x0.z, x0.w, x1.x, x1.y, x1.z, x1.w};
#pragma unroll
            for (int i = 0; i < 8; i++) {
                unsigned long long rai = splat2(ra[i]);
                FMA2(acc[i][0], rai, rb0);
                FMA2(acc[i][1], rai, rb1);
                FMA2(acc[i][2], rai, rb2);
                FMA2(acc[i][3], rai, rb3);
            }
        }
    }

#pragma unroll
    for (int i = 0; i < 8; i++) {
        const int row = m0 + tr * 8 + i;
        const float gs = g_gv[row] * PSCALE;
        float lo, hi;
        asm("mov.b64 {%0, %1}, %2;" : "=f"(lo), "=f"(hi) : "l"(acc[i][0]));
        float v0 = lo * gs, v1 = hi * gs;
        asm("mov.b64 {%0, %1}, %2;" : "=f"(lo), "=f"(hi) : "l"(acc[i][1]));
        float v2 = lo * gs, v3 = hi * gs;
        asm("mov.b64 {%0, %1}, %2;" : "=f"(lo), "=f"(hi) : "l"(acc[i][2]));
        float v4 = lo * gs, v5 = hi * gs;
        asm("mov.b64 {%0, %1}, %2;" : "=f"(lo), "=f"(hi) : "l"(acc[i][3]));
        float v6 = lo * gs, v7 = hi * gs;

        __half2 h01 = __floats2half2_rn(v0, v1);
        __half2 h23 = __floats2half2_rn(v2, v3);
        __half2 h45 = __floats2half2_rn(v4, v5);
        __half2 h67 = __floats2half2_rn(v6, v7);

        uint2 pack0, pack1;
        pack0.x = *(unsigned*)&h01; pack0.y = *(unsigned*)&h23;
        pack1.x = *(unsigned*)&h45; pack1.y = *(unsigned*)&h67;
        uint2* dst = (uint2*)&g_P[(size_t)row * 256 + n0 + tc * 8];
        dst[0] = pack0;
        dst[1] = pack1;
    }
}

// ---------------------------------------------------------------------------
// Kernel 4: SCAN. One CTA per row; coalesced presence-mask scan of Ahat;
// writes compacted u16 neighbor list + denominator. No dependency on P,
// runs concurrently with gemm_kernel on a parallel graph branch.
// ---------------------------------------------------------------------------
__global__ __launch_bounds__(256) void scan_kernel(const float* __restrict__ Ahat) {
    __shared__ int   s_flat[CAP + 64];
    __shared__ int   s_cnt[8];
    __shared__ float s_den[8];
    __shared__ int   s_off[9];

    const int tid = threadIdx.x;
    const int lane = tid & 31;
    const int wid = tid >> 5;
    const size_t row = blockIdx.x;

    const float4* arow = (const float4*)(Ahat + row * NN);
    unsigned mask = 0u;
#pragma unroll
    for (int k = 0; k < 8; k++) {
        float4 v = __ldcs(&arow[wid * 256 + k * 32 + lane]);
        if (v.x > 0.f) mask |= 1u << (4 * k + 0);
        if (v.y > 0.f) mask |= 1u << (4 * k + 1);
        if (v.z > 0.f) mask |= 1u << (4 * k + 2);
        if (v.w > 0.f) mask |= 1u << (4 * k + 3);
    }
    int cnt = __popc(mask);

    int pre = cnt;
#pragma unroll
    for (int o = 1; o < 32; o <<= 1) {
        int n = __shfl_up_sync(0xffffffffu, pre, o);
        if (lane >= o) pre += n;
    }
    if (lane == 31) s_cnt[wid] = pre;
    __syncthreads();
    if (tid == 0) {
        int o = 0;
#pragma unroll
        for (int w = 0; w < 8; w++) { s_off[w] = o; o += s_cnt[w]; }
        s_off[8] = o;
    }
    __syncthreads();

    int off = s_off[wid] + (pre - cnt);
    float denl = 0.f;
    const int cbase = wid * 1024 + lane * 4;
    unsigned m = mask;
    while (m) {
        int b = __ffs(m) - 1;
        int col = cbase + (b >> 2) * 128 + (b & 3);
        if (off < CAP) s_flat[off] = col;
        off++;
        denl += g_gv[col];
        m &= m - 1u;
    }

#pragma unroll
    for (int o = 16; o > 0; o >>= 1) denl += __shfl_xor_sync(0xffffffffu, denl, o);
    if (lane == 0) s_den[wid] = denl;
    __syncthreads();

    int nnz = s_off[8]; if (nnz > CAP) nnz = CAP;
    if (tid < nnz) g_nbr[row][tid] = (unsigned short)s_flat[tid];
    if (tid == 0) {
        g_nnz[row] = nnz;
        g_den[row] = ((s_den[0] + s_den[1]) + (s_den[2] + s_den[3])) +
                     ((s_den[4] + s_den[5]) + (s_den[6] + s_den[7]));
    }
}

// ---------------------------------------------------------------------------
// Kernel 5: gather. out[i] = relu( sum P[j] / (PSCALE * den[i]) )
// One CTA per row; 4 groups x 64 threads; group g handles j==g (mod 4);
// half4 (uint2) loads, fp32 accumulation, fixed-order smem reduction.
// ---------------------------------------------------------------------------
__global__ __launch_bounds__(256) void gather_kernel(float* __restrict__ out) {
    __shared__ int   s_idx[CAP];
    __shared__ float s_part[4 * 256];

    const int tid = threadIdx.x;
    const size_t row = blockIdx.x;

    const int nnz = g_nnz[row];
    const float den = g_den[row];
    if (tid < nnz) s_idx[tid] = g_nbr[row][tid];
    __syncthreads();

    const int g = tid >> 6;    // group 0..3
    const int c = tid & 63;    // half4 (uint2) index within row

    float ax = 0.f, ay = 0.f, az = 0.f, aw = 0.f;
    float bx = 0.f, by = 0.f, bz = 0.f, bw = 0.f;

    int j = g;
    for (; j + 4 < nnz; j += 8) {
        uint2 v0 = __ldg((const uint2*)&g_P[(size_t)s_idx[j + 0] * 256] + c);
        uint2 v1 = __ldg((const uint2*)&g_P[(size_t)s_idx[j + 4] * 256] + c);
        float2 l0 = __half22float2(*(const __half2*)&v0.x);
        float2 h0 = __half22float2(*(const __half2*)&v0.y);
        float2 l1 = __half22float2(*(const __half2*)&v1.x);
        float2 h1 = __half22float2(*(const __half2*)&v1.y);
        ax += l0.x; ay += l0.y; az += h0.x; aw += h0.y;
        bx += l1.x; by += l1.y; bz += h1.x; bw += h1.y;
    }
    for (; j < nnz; j += 4) {
        uint2 v0 = __ldg((const uint2*)&g_P[(size_t)s_idx[j] * 256] + c);
        float2 l0 = __half22float2(*(const __half2*)&v0.x);
        float2 h0 = __half22float2(*(const __half2*)&v0.y);
        ax += l0.x; ay += l0.y; az += h0.x; aw += h0.y;
    }
    ax += bx; ay += by; az += bz; aw += bw;

    *(float4*)&s_part[g * 256 + c * 4] = make_float4(ax, ay, az, aw);
    __syncthreads();

    const float invd = 1.f / (den * PSCALE);
    float r = ((s_part[0 * 256 + tid] + s_part[1 * 256 + tid]) +
               (s_part[2 * 256 + tid] + s_part[3 * 256 + tid]));
    out[row * 256 + tid] = fmaxf(r * invd, 0.f);
}

// ---------------------------------------------------------------------------
// Launch: prep -> fdst -> gv -> [ gemm (stream2) || scan (main) ] -> gather
// ---------------------------------------------------------------------------
extern "C" void kernel_launch(void* const* d_in, const int* in_sizes, int n_in,
                              void* d_out, int out_size) {
    (void)in_sizes; (void)n_in; (void)out_size;
    const float* node = (const float*)d_in[0];
    const float* Ahat = (const float*)d_in[1];
    const float* w    = (const float*)d_in[2];
    const float* w_a  = (const float*)d_in[3];
    const float* a    = (const float*)d_in[4];
    float* out = (float*)d_out;

    static cudaStream_t s2 = nullptr;
    static cudaEvent_t e_fork = nullptr, e_join = nullptr;
    if (s2 == nullptr) {
        cudaStreamCreateWithFlags(&s2, cudaStreamNonBlocking);
        cudaEventCreateWithFlags(&e_fork, cudaEventDisableTiming);
        cudaEventCreateWithFlags(&e_join, cudaEventDisableTiming);
    }

    prep_kernel<<<1, 1024>>>(w, w_a, a);
    fdst_kernel<<<NN / 8, 256>>>(node);
    gv_kernel<<<NN / 1024, 1024>>>();

    cudaEventRecord(e_fork, 0);
    cudaStreamWaitEvent(s2, e_fork, 0);
    dim3 ggrid(2, 64);
    gemm_kernel<<<ggrid, 256, 0, s2>>>(node, w);
    cudaEventRecord(e_join, s2);

    scan_kernel<<<NN, 256>>>(Ahat);

    cudaStreamWaitEvent(0, e_join, 0);
    gather_kernel<<<NN, 256>>>(out);
}